// round 9
// baseline (speedup 1.0000x reference)
#include <cuda_runtime.h>
#include <cuda_fp16.h>
#include <math.h>

#define NN 100000
#define EE 3200000
#define F_IN 128
#define H1 32
#define H2 64
#define GG 256
#define ACT 64

// ---------------- scratch (static device globals; no allocation) ----------------
__device__ int    g_deg[NN];
__device__ float  g_dinv[NN];
__device__ int    g_off[NN];     // start of each node's CSR range
__device__ int    g_cur[NN];     // fill cursor; after scatter == end of range
__device__ int    g_csr[EE];
__device__ int    g_counter[1];
__device__ __half g_hn1[NN * H1];   // hn1 = dinv * (x @ W1)   [N,32] fp16
__device__ __half g_p[NN * H1];     // p   = dinv * h1         [N,32] fp16
__device__ float  g_pool[GG * H2];

// ---------------- degree (int4-vectorized edge reads) ----------------
__global__ void k_deg(const int* __restrict__ dst) {
    int i = blockIdx.x * blockDim.x + threadIdx.x;   // over EE/4
    if (i < EE / 4) {
        int4 d4 = ((const int4*)dst)[i];
        atomicAdd(&g_deg[d4.x], 1);
        atomicAdd(&g_deg[d4.y], 1);
        atomicAdd(&g_deg[d4.z], 1);
        atomicAdd(&g_deg[d4.w], 1);
    }
}

// ---------------- offsets: warp scan + one atomic per warp; also dinv ----------------
__global__ void k_offsets() {
    int node = blockIdx.x * blockDim.x + threadIdx.x;
    int lane = threadIdx.x & 31;
    int d = (node < NN) ? g_deg[node] : 0;
    if (node < NN) g_dinv[node] = rsqrtf((float)(d + 1));
    // inclusive warp scan
    int s = d;
#pragma unroll
    for (int o = 1; o < 32; o <<= 1) {
        int v = __shfl_up_sync(0xffffffffu, s, o);
        if (lane >= o) s += v;
    }
    int total = __shfl_sync(0xffffffffu, s, 31);
    int base = 0;
    if (lane == 31) base = atomicAdd(&g_counter[0], total);
    base = __shfl_sync(0xffffffffu, base, 31);
    if (node < NN) {
        int off = base + s - d;   // exclusive
        g_off[node] = off;
        g_cur[node] = off;
    }
}

__global__ void k_scatter(const int* __restrict__ src, const int* __restrict__ dst) {
    int i = blockIdx.x * blockDim.x + threadIdx.x;   // over EE/4
    if (i < EE / 4) {
        int4 s4 = ((const int4*)src)[i];
        int4 d4 = ((const int4*)dst)[i];
        g_csr[atomicAdd(&g_cur[d4.x], 1)] = s4.x;
        g_csr[atomicAdd(&g_cur[d4.y], 1)] = s4.y;
        g_csr[atomicAdd(&g_cur[d4.z], 1)] = s4.z;
        g_csr[atomicAdd(&g_cur[d4.w], 1)] = s4.w;
    }
}

// ---------------- layer 1 GEMM (tiled): hn1 = fp16(dinv * (x @ W1)) ----------------
#define TILE_N 64
__global__ __launch_bounds__(256) void k_gemm1(const float* __restrict__ x,
                                               const float* __restrict__ W1) {
    __shared__ float xs[TILE_N][132];        // padded: conflict-free column reads
    __shared__ float Ws[F_IN][H1];           // 16KB, [k][c]
    int base = blockIdx.x * TILE_N;
    for (int i = threadIdx.x; i < (F_IN * H1) / 4; i += 256)
        ((float4*)Ws)[i] = ((const float4*)W1)[i];
    for (int i = threadIdx.x; i < TILE_N * 32; i += 256) {
        int r = i >> 5, c4 = i & 31;
        int row = base + r;
        float4 v = (row < NN) ? ((const float4*)x)[row * 32 + c4]
                              : make_float4(0.f, 0.f, 0.f, 0.f);
        *(float4*)&xs[r][c4 * 4] = v;
    }
    __syncthreads();
    int t = threadIdx.x;
    int cg = (t & 7) * 4;        // 4 channels
    int n0 = (t >> 3) * 2;       // 2 local nodes
    float a0[4] = {0.f, 0.f, 0.f, 0.f};
    float a1[4] = {0.f, 0.f, 0.f, 0.f};
#pragma unroll 8
    for (int k = 0; k < F_IN; k++) {
        float4 w = *(const float4*)&Ws[k][cg];
        float x0 = xs[n0][k];
        float x1 = xs[n0 + 1][k];
        a0[0] = fmaf(x0, w.x, a0[0]); a0[1] = fmaf(x0, w.y, a0[1]);
        a0[2] = fmaf(x0, w.z, a0[2]); a0[3] = fmaf(x0, w.w, a0[3]);
        a1[0] = fmaf(x1, w.x, a1[0]); a1[1] = fmaf(x1, w.y, a1[1]);
        a1[2] = fmaf(x1, w.z, a1[2]); a1[3] = fmaf(x1, w.w, a1[3]);
    }
    __half2* hn1 = (__half2*)g_hn1;
    int r0 = base + n0;
    if (r0 < NN) {
        float d = g_dinv[r0];
        hn1[r0 * 16 + (cg >> 1)]     = __floats2half2_rn(d * a0[0], d * a0[1]);
        hn1[r0 * 16 + (cg >> 1) + 1] = __floats2half2_rn(d * a0[2], d * a0[3]);
    }
    int r1 = r0 + 1;
    if (r1 < NN) {
        float d = g_dinv[r1];
        hn1[r1 * 16 + (cg >> 1)]     = __floats2half2_rn(d * a1[0], d * a1[1]);
        hn1[r1 * 16 + (cg >> 1) + 1] = __floats2half2_rn(d * a1[2], d * a1[3]);
    }
}

// ---------------- shared gather core ----------------
// Warp per node. lane = (side<<4)|pair. Per chunk: ONE coalesced warp-LDG
// pulls 32 CSR indices; shfl distributes them. side s consumes edges 2j+s.
// Feature rows gathered as __half2 per lane (16 lanes = 64B row, 2 edges
// in flight per warp-LDG). shfl_xor(16) merges side accumulators at the end.
__device__ __forceinline__ float2 gather_sum(const __half2* __restrict__ H,
                                             int node, int pair, int side, int lane) {
    float2 acc = make_float2(0.f, 0.f);
    if (side == 0) {  // self loop
        acc = __half22float2(H[node * 16 + pair]);
    }
    int e = g_off[node], end = g_cur[node];
    while (e < end) {
        int rem = end - e;
        int idx = 0;
        if (lane < rem) idx = g_csr[e + lane];
        if (rem >= 32) {
#pragma unroll
            for (int j = 0; j < 16; j++) {
                int s = __shfl_sync(0xffffffffu, idx, 2 * j + side);
                float2 f = __half22float2(H[s * 16 + pair]);
                acc.x += f.x; acc.y += f.y;
            }
        } else {
#pragma unroll
            for (int j = 0; j < 16; j++) {
                int ed = 2 * j + side;
                int s = __shfl_sync(0xffffffffu, idx, ed);
                if (ed < rem) {
                    float2 f = __half22float2(H[s * 16 + pair]);
                    acc.x += f.x; acc.y += f.y;
                }
            }
        }
        e += 32;
    }
    acc.x += __shfl_xor_sync(0xffffffffu, acc.x, 16);
    acc.y += __shfl_xor_sync(0xffffffffu, acc.y, 16);
    return acc;
}

// ---------------- agg1: p = fp16( dinv * leaky(dinv*sum + b1) ) ----------------
__global__ __launch_bounds__(256) void k_agg1(const float* __restrict__ b1) {
    int warp = (blockIdx.x * 256 + threadIdx.x) >> 5;
    int lane = threadIdx.x & 31;
    if (warp >= NN) return;
    int pair = lane & 15, side = lane >> 4;
    float2 acc = gather_sum((const __half2*)g_hn1, warp, pair, side, lane);
    float d = g_dinv[warp];
    float2 bb = ((const float2*)b1)[pair];
    float rx = d * acc.x + bb.x;
    float ry = d * acc.y + bb.y;
    rx = (rx > 0.f) ? rx : 0.1f * rx;
    ry = (ry > 0.f) ? ry : 0.1f * ry;
    if (side == 0)
        ((__half2*)g_p)[warp * 16 + pair] = __floats2half2_rn(d * rx, d * ry);
}

// ---------------- sign-split float atomic max (no-return -> RED) ----------------
__device__ __forceinline__ void atomicMaxFloat(float* addr, float val) {
    if (val >= 0.f)
        atomicMax((int*)addr, __float_as_int(val));
    else
        atomicMin((unsigned int*)addr, __float_as_uint(val));
}

// ---------------- agg2: h2 = dinv*(q@W2) + b2 ; fused max pool ----------------
__global__ __launch_bounds__(256) void k_agg2(const float* __restrict__ W2,
                                              const float* __restrict__ b2,
                                              const int* __restrict__ batch) {
    __shared__ float2 W2s[H1 * 32];  // W2 [32][64] row-major == [32][32] float2
    for (int i = threadIdx.x; i < H1 * 32; i += 256)
        W2s[i] = ((const float2*)W2)[i];
    __syncthreads();
    int warp = (blockIdx.x * 256 + threadIdx.x) >> 5;
    int lane = threadIdx.x & 31;
    if (warp >= NN) return;
    int pair = lane & 15, side = lane >> 4;
    float2 acc = gather_sum((const __half2*)g_p, warp, pair, side, lane);
    // q[2j]=acc.x@lane j(mod16), q[2j+1]=acc.y@lane j; lane owns out ch 2*lane,2*lane+1
    float z0 = 0.f, z1 = 0.f;
#pragma unroll
    for (int k = 0; k < H1; k++) {
        float qk = __shfl_sync(0xffffffffu, (k & 1) ? acc.y : acc.x, (k >> 1) & 15);
        float2 w = W2s[k * 32 + lane];
        z0 = fmaf(qk, w.x, z0);
        z1 = fmaf(qk, w.y, z1);
    }
    float d = g_dinv[warp];
    float2 bb = ((const float2*)b2)[lane];
    float ox = d * z0 + bb.x;
    float oy = d * z1 + bb.y;
    int gidx = batch[warp];
    atomicMaxFloat(&g_pool[gidx * H2 + 2 * lane], ox);
    atomicMaxFloat(&g_pool[gidx * H2 + 2 * lane + 1], oy);
}

// ---------------- MLP head: one block per graph ----------------
__global__ __launch_bounds__(128) void k_mlp(const float* __restrict__ l1W, const float* __restrict__ l1b,
                                             const float* __restrict__ l2W, const float* __restrict__ l2b,
                                             const float* __restrict__ l3W, const float* __restrict__ l3b,
                                             float* __restrict__ out) {
    __shared__ float gv[H2];
    __shared__ float z1[128];
    __shared__ float z2[64];
    int g = blockIdx.x, t = threadIdx.x;
    if (t < H2) gv[t] = g_pool[g * H2 + t];
    __syncthreads();
    {
        float s = 0.f;
#pragma unroll
        for (int k = 0; k < H2; k++) s = fmaf(gv[k], l1W[k * 128 + t], s);
        s += l1b[t];
        z1[t] = (s > 0.f) ? s : 0.1f * s;
    }
    __syncthreads();
    if (t < 64) {
        float s = 0.f;
#pragma unroll
        for (int k = 0; k < 128; k++) s = fmaf(z1[k], l2W[k * 64 + t], s);
        s += l2b[t];
        z2[t] = (s > 0.f) ? s : 0.1f * s;
    }
    __syncthreads();
    if (t < ACT) {
        float s = 0.f;
#pragma unroll
        for (int k = 0; k < 64; k++) s = fmaf(z2[k], l3W[k * ACT + t], s);
        out[g * ACT + t] = s + l3b[t];
    }
}

// ---------------- launch ----------------
extern "C" void kernel_launch(void* const* d_in, const int* in_sizes, int n_in,
                              void* d_out, int out_size) {
    const float* x    = (const float*)d_in[0];
    const int*   ei   = (const int*)d_in[1];   // [2,E]
    const int*   bat  = (const int*)d_in[2];
    const float* W1   = (const float*)d_in[3];
    const float* b1   = (const float*)d_in[4];
    const float* W2   = (const float*)d_in[5];
    const float* b2   = (const float*)d_in[6];
    const float* l1W  = (const float*)d_in[7];
    const float* l1b  = (const float*)d_in[8];
    const float* l2W  = (const float*)d_in[9];
    const float* l2b  = (const float*)d_in[10];
    const float* l3W  = (const float*)d_in[11];
    const float* l3b  = (const float*)d_in[12];
    float* out = (float*)d_out;
    const int* src = ei;
    const int* dst = ei + EE;

    // async memset init (graph-capturable, not an allocation)
    void *p_deg = nullptr, *p_cnt = nullptr, *p_pool = nullptr;
    cudaGetSymbolAddress(&p_deg, g_deg);
    cudaGetSymbolAddress(&p_cnt, g_counter);
    cudaGetSymbolAddress(&p_pool, g_pool);
    cudaMemsetAsync(p_deg, 0, NN * sizeof(int));
    cudaMemsetAsync(p_cnt, 0, sizeof(int));
    cudaMemsetAsync(p_pool, 0xFF, GG * H2 * sizeof(float));  // NaN-bits: valid init for sign-split max

    const int NB_E4 = (EE / 4 + 255) / 256;       // 3125
    const int NB_N  = (NN + 255) / 256;           // 391
    const int NB_W  = (NN + 7) / 8;               // 12500 (warp per node)
    const int NB_G1 = (NN + TILE_N - 1) / TILE_N; // 1563

    k_deg<<<NB_E4, 256>>>(dst);
    k_offsets<<<NB_N, 256>>>();
    k_scatter<<<NB_E4, 256>>>(src, dst);

    k_gemm1<<<NB_G1, 256>>>(x, W1);
    k_agg1<<<NB_W, 256>>>(b1);
    k_agg2<<<NB_W, 256>>>(W2, b2, bat);

    k_mlp<<<GG, 128>>>(l1W, l1b, l2W, l2b, l3W, l3b, out);
}

// round 10
// speedup vs baseline: 1.0793x; 1.0793x over previous
#include <cuda_runtime.h>
#include <cuda_fp16.h>
#include <math.h>

#define NN 100000
#define EE 3200000
#define F_IN 128
#define H1 32
#define H2 64
#define GG 256
#define ACT 64

// ---------------- scratch (static device globals; no allocation) ----------------
__device__ int    g_deg[NN];
__device__ float  g_dinv[NN];
__device__ int    g_off[NN];     // start of each node's CSR range
__device__ int    g_cur[NN];     // fill cursor; after scatter == end of range
__device__ int    g_csr[EE];
__device__ int    g_counter[1];
__device__ __half g_hn1[NN * H1];   // hn1 = dinv * (x @ W1)   [N,32] fp16
__device__ __half g_p[NN * H1];     // p   = dinv * h1         [N,32] fp16
__device__ float  g_pool[GG * H2];

// ---------------- degree (int4-vectorized edge reads) ----------------
__global__ void k_deg(const int* __restrict__ dst) {
    int i = blockIdx.x * blockDim.x + threadIdx.x;   // over EE/4
    if (i < EE / 4) {
        int4 d4 = ((const int4*)dst)[i];
        atomicAdd(&g_deg[d4.x], 1);
        atomicAdd(&g_deg[d4.y], 1);
        atomicAdd(&g_deg[d4.z], 1);
        atomicAdd(&g_deg[d4.w], 1);
    }
}

// ---------------- offsets: warp scan + one atomic per warp; also dinv ----------------
__global__ void k_offsets() {
    int node = blockIdx.x * blockDim.x + threadIdx.x;
    int lane = threadIdx.x & 31;
    int d = (node < NN) ? g_deg[node] : 0;
    if (node < NN) g_dinv[node] = rsqrtf((float)(d + 1));
    int s = d;
#pragma unroll
    for (int o = 1; o < 32; o <<= 1) {
        int v = __shfl_up_sync(0xffffffffu, s, o);
        if (lane >= o) s += v;
    }
    int total = __shfl_sync(0xffffffffu, s, 31);
    int base = 0;
    if (lane == 31) base = atomicAdd(&g_counter[0], total);
    base = __shfl_sync(0xffffffffu, base, 31);
    if (node < NN) {
        int off = base + s - d;   // exclusive
        g_off[node] = off;
        g_cur[node] = off;
    }
}

__global__ void k_scatter(const int* __restrict__ src, const int* __restrict__ dst) {
    int i = blockIdx.x * blockDim.x + threadIdx.x;   // over EE/4
    if (i < EE / 4) {
        int4 s4 = ((const int4*)src)[i];
        int4 d4 = ((const int4*)dst)[i];
        g_csr[atomicAdd(&g_cur[d4.x], 1)] = s4.x;
        g_csr[atomicAdd(&g_cur[d4.y], 1)] = s4.y;
        g_csr[atomicAdd(&g_cur[d4.z], 1)] = s4.z;
        g_csr[atomicAdd(&g_cur[d4.w], 1)] = s4.w;
    }
}

// ---------------- layer 1 GEMM: hn1 = fp16(dinv * (x @ W1)), K-split ----------------
#define TILE_N 64
__global__ __launch_bounds__(256) void k_gemm1(const float* __restrict__ x,
                                               const float* __restrict__ W1) {
    __shared__ float xs[TILE_N][68];     // 64 cols per stage + pad -> 17.4KB
    __shared__ float Ws[F_IN][H1];       // 16KB
    int base = blockIdx.x * TILE_N;
    int t = threadIdx.x;
    for (int i = t; i < (F_IN * H1) / 4; i += 256)
        ((float4*)Ws)[i] = ((const float4*)W1)[i];
    int cg = (t & 7) * 4;        // 4 output channels
    int n0 = (t >> 3) * 2;       // 2 local nodes
    float a0[4] = {0.f, 0.f, 0.f, 0.f};
    float a1[4] = {0.f, 0.f, 0.f, 0.f};
#pragma unroll
    for (int stage = 0; stage < 2; stage++) {
        float4 v[4];
#pragma unroll
        for (int b = 0; b < 4; b++) {   // batch 4 LDG.128 up front (MLP)
            int j = t + 256 * b;
            int r = j >> 4, c4 = j & 15;
            int row = base + r;
            v[b] = (row < NN) ? ((const float4*)x)[row * 32 + stage * 16 + c4]
                              : make_float4(0.f, 0.f, 0.f, 0.f);
        }
        __syncthreads();  // previous stage's reads done (also orders Ws stores)
#pragma unroll
        for (int b = 0; b < 4; b++) {
            int j = t + 256 * b;
            int r = j >> 4, c4 = j & 15;
            *(float4*)&xs[r][c4 * 4] = v[b];
        }
        __syncthreads();
#pragma unroll 8
        for (int kk = 0; kk < 64; kk++) {
            int k = stage * 64 + kk;
            float4 w = *(const float4*)&Ws[k][cg];
            float x0 = xs[n0][kk];
            float x1 = xs[n0 + 1][kk];
            a0[0] = fmaf(x0, w.x, a0[0]); a0[1] = fmaf(x0, w.y, a0[1]);
            a0[2] = fmaf(x0, w.z, a0[2]); a0[3] = fmaf(x0, w.w, a0[3]);
            a1[0] = fmaf(x1, w.x, a1[0]); a1[1] = fmaf(x1, w.y, a1[1]);
            a1[2] = fmaf(x1, w.z, a1[2]); a1[3] = fmaf(x1, w.w, a1[3]);
        }
    }
    __half2* hn1 = (__half2*)g_hn1;
    int r0 = base + n0;
    if (r0 < NN) {
        float d = g_dinv[r0];
        hn1[r0 * 16 + (cg >> 1)]     = __floats2half2_rn(d * a0[0], d * a0[1]);
        hn1[r0 * 16 + (cg >> 1) + 1] = __floats2half2_rn(d * a0[2], d * a0[3]);
    }
    int r1 = r0 + 1;
    if (r1 < NN) {
        float d = g_dinv[r1];
        hn1[r1 * 16 + (cg >> 1)]     = __floats2half2_rn(d * a1[0], d * a1[1]);
        hn1[r1 * 16 + (cg >> 1) + 1] = __floats2half2_rn(d * a1[2], d * a1[3]);
    }
}

// ---------------- gather core: 4 edges in flight per warp ----------------
// lane = (side<<3)|q : q = channel quad (ch 4q..4q+3, 8B), side = edge slot 0..3.
// Feature row (64B) covered by 8 lanes; one warp-LDG = 4 rows.
// Indices: warp-uniform int4 LDG at 4-aligned CSR offsets (1 LDG = 4 edges).
__device__ __forceinline__ int pick4(int4 v, int side) {
    return (side == 0) ? v.x : (side == 1) ? v.y : (side == 2) ? v.z : v.w;
}

__device__ __forceinline__ void addrow(const __half* __restrict__ H, int s, int q,
                                       float& a0, float& a1, float& a2, float& a3) {
    uint2 w = *(const uint2*)(H + s * 32 + q * 4);
    float2 f0 = __half22float2(*(__half2*)&w.x);
    float2 f1 = __half22float2(*(__half2*)&w.y);
    a0 += f0.x; a1 += f0.y; a2 += f1.x; a3 += f1.y;
}

__device__ __forceinline__ void gather4(const __half* __restrict__ H, int node,
                                        int q, int side,
                                        float& a0, float& a1, float& a2, float& a3) {
    if (side == 0) addrow(H, node, q, a0, a1, a2, a3);   // self loop
    int e = g_off[node], end = g_cur[node];
    // prologue: up to 3 edges to reach 4-alignment
    int r = (4 - (e & 3)) & 3;
    if (r > end - e) r = end - e;
    if (r > 0) {
        if (side < r) {
            int s = g_csr[e + side];
            addrow(H, s, q, a0, a1, a2, a3);
        }
        e += r;
    }
    // main: 8 edges per iter (2 uniform int4 idx LDGs + 2 feature LDGs)
    for (; e + 8 <= end; e += 8) {
        int4 A = *(const int4*)(g_csr + e);
        int4 B = *(const int4*)(g_csr + e + 4);
        int sA = pick4(A, side);
        int sB = pick4(B, side);
        addrow(H, sA, q, a0, a1, a2, a3);
        addrow(H, sB, q, a0, a1, a2, a3);
    }
    if (e + 4 <= end) {
        int4 A = *(const int4*)(g_csr + e);
        addrow(H, pick4(A, side), q, a0, a1, a2, a3);
        e += 4;
    }
    int rem = end - e;   // 0..3
    if (side < rem) {
        int s = g_csr[e + side];
        addrow(H, s, q, a0, a1, a2, a3);
    }
    // merge the 4 side groups: every lane ends with the full sum for its quad
    a0 += __shfl_xor_sync(0xffffffffu, a0, 8);
    a1 += __shfl_xor_sync(0xffffffffu, a1, 8);
    a2 += __shfl_xor_sync(0xffffffffu, a2, 8);
    a3 += __shfl_xor_sync(0xffffffffu, a3, 8);
    a0 += __shfl_xor_sync(0xffffffffu, a0, 16);
    a1 += __shfl_xor_sync(0xffffffffu, a1, 16);
    a2 += __shfl_xor_sync(0xffffffffu, a2, 16);
    a3 += __shfl_xor_sync(0xffffffffu, a3, 16);
}

// ---------------- agg1: p = fp16( dinv * leaky(dinv*sum + b1) ) ----------------
__global__ __launch_bounds__(256) void k_agg1(const float* __restrict__ b1) {
    int warp = (blockIdx.x * 256 + threadIdx.x) >> 5;
    int lane = threadIdx.x & 31;
    if (warp >= NN) return;
    int q = lane & 7, side = lane >> 3;
    float a0 = 0.f, a1 = 0.f, a2 = 0.f, a3 = 0.f;
    gather4(g_hn1, warp, q, side, a0, a1, a2, a3);
    float d = g_dinv[warp];
    float4 bb = ((const float4*)b1)[q];
    float r0 = d * a0 + bb.x;
    float r1 = d * a1 + bb.y;
    float r2 = d * a2 + bb.z;
    float r3 = d * a3 + bb.w;
    r0 = (r0 > 0.f) ? r0 : 0.1f * r0;
    r1 = (r1 > 0.f) ? r1 : 0.1f * r1;
    r2 = (r2 > 0.f) ? r2 : 0.1f * r2;
    r3 = (r3 > 0.f) ? r3 : 0.1f * r3;
    if (side == 0) {
        __half2 h0 = __floats2half2_rn(d * r0, d * r1);
        __half2 h1 = __floats2half2_rn(d * r2, d * r3);
        uint2 u;
        u.x = *(unsigned int*)&h0;
        u.y = *(unsigned int*)&h1;
        *(uint2*)(g_p + warp * 32 + q * 4) = u;
    }
}

// ---------------- sign-split float atomic max (no-return -> RED) ----------------
__device__ __forceinline__ void atomicMaxFloat(float* addr, float val) {
    if (val >= 0.f)
        atomicMax((int*)addr, __float_as_int(val));
    else
        atomicMin((unsigned int*)addr, __float_as_uint(val));
}

// ---------------- agg2: h2 = dinv*(q@W2) + b2 ; fused max pool ----------------
__global__ __launch_bounds__(256) void k_agg2(const float* __restrict__ W2,
                                              const float* __restrict__ b2,
                                              const int* __restrict__ batch) {
    __shared__ float2 W2s[H1 * 32];  // W2 [32][64] row-major == [32][32] float2
    for (int i = threadIdx.x; i < H1 * 32; i += 256)
        W2s[i] = ((const float2*)W2)[i];
    __syncthreads();
    int warp = (blockIdx.x * 256 + threadIdx.x) >> 5;
    int lane = threadIdx.x & 31;
    if (warp >= NN) return;
    int q = lane & 7, side = lane >> 3;
    float a0 = 0.f, a1 = 0.f, a2 = 0.f, a3 = 0.f;
    gather4(g_p, warp, q, side, a0, a1, a2, a3);
    // q-vector element k (0..31) lives in reg a[k&3] of lane (k>>2) (all side groups)
    float z0 = 0.f, z1 = 0.f;
#pragma unroll
    for (int k = 0; k < H1; k++) {
        int j = k & 3;
        float srcv = (j == 0) ? a0 : (j == 1) ? a1 : (j == 2) ? a2 : a3;
        float qk = __shfl_sync(0xffffffffu, srcv, k >> 2);
        float2 w = W2s[k * 32 + lane];
        z0 = fmaf(qk, w.x, z0);
        z1 = fmaf(qk, w.y, z1);
    }
    float d = g_dinv[warp];
    float2 bb = ((const float2*)b2)[lane];
    float ox = d * z0 + bb.x;
    float oy = d * z1 + bb.y;
    int gidx = batch[warp];
    atomicMaxFloat(&g_pool[gidx * H2 + 2 * lane], ox);
    atomicMaxFloat(&g_pool[gidx * H2 + 2 * lane + 1], oy);
}

// ---------------- MLP head: one block per graph ----------------
__global__ __launch_bounds__(128) void k_mlp(const float* __restrict__ l1W, const float* __restrict__ l1b,
                                             const float* __restrict__ l2W, const float* __restrict__ l2b,
                                             const float* __restrict__ l3W, const float* __restrict__ l3b,
                                             float* __restrict__ out) {
    __shared__ float gv[H2];
    __shared__ float z1[128];
    __shared__ float z2[64];
    int g = blockIdx.x, t = threadIdx.x;
    if (t < H2) gv[t] = g_pool[g * H2 + t];
    __syncthreads();
    {
        float s = 0.f;
#pragma unroll
        for (int k = 0; k < H2; k++) s = fmaf(gv[k], l1W[k * 128 + t], s);
        s += l1b[t];
        z1[t] = (s > 0.f) ? s : 0.1f * s;
    }
    __syncthreads();
    if (t < 64) {
        float s = 0.f;
#pragma unroll
        for (int k = 0; k < 128; k++) s = fmaf(z1[k], l2W[k * 64 + t], s);
        s += l2b[t];
        z2[t] = (s > 0.f) ? s : 0.1f * s;
    }
    __syncthreads();
    if (t < ACT) {
        float s = 0.f;
#pragma unroll
        for (int k = 0; k < 64; k++) s = fmaf(z2[k], l3W[k * ACT + t], s);
        out[g * ACT + t] = s + l3b[t];
    }
}

// ---------------- launch ----------------
extern "C" void kernel_launch(void* const* d_in, const int* in_sizes, int n_in,
                              void* d_out, int out_size) {
    const float* x    = (const float*)d_in[0];
    const int*   ei   = (const int*)d_in[1];   // [2,E]
    const int*   bat  = (const int*)d_in[2];
    const float* W1   = (const float*)d_in[3];
    const float* b1   = (const float*)d_in[4];
    const float* W2   = (const float*)d_in[5];
    const float* b2   = (const float*)d_in[6];
    const float* l1W  = (const float*)d_in[7];
    const float* l1b  = (const float*)d_in[8];
    const float* l2W  = (const float*)d_in[9];
    const float* l2b  = (const float*)d_in[10];
    const float* l3W  = (const float*)d_in[11];
    const float* l3b  = (const float*)d_in[12];
    float* out = (float*)d_out;
    const int* src = ei;
    const int* dst = ei + EE;

    void *p_deg = nullptr, *p_cnt = nullptr, *p_pool = nullptr;
    cudaGetSymbolAddress(&p_deg, g_deg);
    cudaGetSymbolAddress(&p_cnt, g_counter);
    cudaGetSymbolAddress(&p_pool, g_pool);
    cudaMemsetAsync(p_deg, 0, NN * sizeof(int));
    cudaMemsetAsync(p_cnt, 0, sizeof(int));
    cudaMemsetAsync(p_pool, 0xFF, GG * H2 * sizeof(float));  // NaN-bits: valid init for sign-split max

    const int NB_E4 = (EE / 4 + 255) / 256;       // 3125
    const int NB_N  = (NN + 255) / 256;           // 391
    const int NB_W  = (NN + 7) / 8;               // 12500 (warp per node)
    const int NB_G1 = (NN + TILE_N - 1) / TILE_N; // 1563

    k_deg<<<NB_E4, 256>>>(dst);
    k_offsets<<<NB_N, 256>>>();
    k_scatter<<<NB_E4, 256>>>(src, dst);

    k_gemm1<<<NB_G1, 256>>>(x, W1);
    k_agg1<<<NB_W, 256>>>(b1);
    k_agg2<<<NB_W, 256>>>(W2, b2, bat);

    k_mlp<<<GG, 128>>>(l1W, l1b, l2W, l2b, l3W, l3b, out);
}

// round 11
// speedup vs baseline: 1.1270x; 1.0441x over previous
#include <cuda_runtime.h>
#include <cuda_fp16.h>
#include <math.h>

#define NN 100000
#define EE 3200000
#define F_IN 128
#define H1 32
#define H2 64
#define GG 256
#define ACT 64

// ---------------- scratch (static device globals; no allocation) ----------------
__device__ int    g_deg[NN];
__device__ float  g_dinv[NN];
__device__ int    g_off[NN];     // start of each node's CSR range
__device__ int    g_cur[NN];     // fill cursor; after scatter == end of range
__device__ int    g_csr[EE];
__device__ int    g_counter[1];
__device__ __half g_hn1[NN * H1];   // hn1 = dinv * (x @ W1)   [N,32] fp16
__device__ __half g_p[NN * H1];     // p   = dinv * h1         [N,32] fp16
__device__ float  g_pool[GG * H2];

// ---------------- degree (int4-vectorized edge reads) ----------------
__global__ void k_deg(const int* __restrict__ dst) {
    int i = blockIdx.x * blockDim.x + threadIdx.x;   // over EE/4
    if (i < EE / 4) {
        int4 d4 = ((const int4*)dst)[i];
        atomicAdd(&g_deg[d4.x], 1);
        atomicAdd(&g_deg[d4.y], 1);
        atomicAdd(&g_deg[d4.z], 1);
        atomicAdd(&g_deg[d4.w], 1);
    }
}

// ---------------- offsets: warp scan + one atomic per warp; also dinv ----------------
__global__ void k_offsets() {
    int node = blockIdx.x * blockDim.x + threadIdx.x;
    int lane = threadIdx.x & 31;
    int d = (node < NN) ? g_deg[node] : 0;
    if (node < NN) g_dinv[node] = rsqrtf((float)(d + 1));
    int s = d;
#pragma unroll
    for (int o = 1; o < 32; o <<= 1) {
        int v = __shfl_up_sync(0xffffffffu, s, o);
        if (lane >= o) s += v;
    }
    int total = __shfl_sync(0xffffffffu, s, 31);
    int base = 0;
    if (lane == 31) base = atomicAdd(&g_counter[0], total);
    base = __shfl_sync(0xffffffffu, base, 31);
    if (node < NN) {
        int off = base + s - d;   // exclusive
        g_off[node] = off;
        g_cur[node] = off;
    }
}

__global__ void k_scatter(const int* __restrict__ src, const int* __restrict__ dst) {
    int i = blockIdx.x * blockDim.x + threadIdx.x;   // over EE/4
    if (i < EE / 4) {
        int4 s4 = ((const int4*)src)[i];
        int4 d4 = ((const int4*)dst)[i];
        g_csr[atomicAdd(&g_cur[d4.x], 1)] = s4.x;
        g_csr[atomicAdd(&g_cur[d4.y], 1)] = s4.y;
        g_csr[atomicAdd(&g_cur[d4.z], 1)] = s4.z;
        g_csr[atomicAdd(&g_cur[d4.w], 1)] = s4.w;
    }
}

// ---------------- layer 1 GEMM: hn1 = fp16(dinv * (x @ W1)), K-split ----------------
#define TILE_N 64
__global__ __launch_bounds__(256) void k_gemm1(const float* __restrict__ x,
                                               const float* __restrict__ W1) {
    __shared__ float xs[TILE_N][68];     // 64 cols per stage + pad -> 17.4KB
    __shared__ float Ws[F_IN][H1];       // 16KB
    int base = blockIdx.x * TILE_N;
    int t = threadIdx.x;
    for (int i = t; i < (F_IN * H1) / 4; i += 256)
        ((float4*)Ws)[i] = ((const float4*)W1)[i];
    int cg = (t & 7) * 4;        // 4 output channels
    int n0 = (t >> 3) * 2;       // 2 local nodes
    float a0[4] = {0.f, 0.f, 0.f, 0.f};
    float a1[4] = {0.f, 0.f, 0.f, 0.f};
#pragma unroll
    for (int stage = 0; stage < 2; stage++) {
        float4 v[4];
#pragma unroll
        for (int b = 0; b < 4; b++) {   // batch 4 LDG.128 up front (MLP)
            int j = t + 256 * b;
            int r = j >> 4, c4 = j & 15;
            int row = base + r;
            v[b] = (row < NN) ? ((const float4*)x)[row * 32 + stage * 16 + c4]
                              : make_float4(0.f, 0.f, 0.f, 0.f);
        }
        __syncthreads();  // previous stage's reads done (also orders Ws stores)
#pragma unroll
        for (int b = 0; b < 4; b++) {
            int j = t + 256 * b;
            int r = j >> 4, c4 = j & 15;
            *(float4*)&xs[r][c4 * 4] = v[b];
        }
        __syncthreads();
#pragma unroll 8
        for (int kk = 0; kk < 64; kk++) {
            int k = stage * 64 + kk;
            float4 w = *(const float4*)&Ws[k][cg];
            float x0 = xs[n0][kk];
            float x1 = xs[n0 + 1][kk];
            a0[0] = fmaf(x0, w.x, a0[0]); a0[1] = fmaf(x0, w.y, a0[1]);
            a0[2] = fmaf(x0, w.z, a0[2]); a0[3] = fmaf(x0, w.w, a0[3]);
            a1[0] = fmaf(x1, w.x, a1[0]); a1[1] = fmaf(x1, w.y, a1[1]);
            a1[2] = fmaf(x1, w.z, a1[2]); a1[3] = fmaf(x1, w.w, a1[3]);
        }
    }
    __half2* hn1 = (__half2*)g_hn1;
    int r0 = base + n0;
    if (r0 < NN) {
        float d = g_dinv[r0];
        hn1[r0 * 16 + (cg >> 1)]     = __floats2half2_rn(d * a0[0], d * a0[1]);
        hn1[r0 * 16 + (cg >> 1) + 1] = __floats2half2_rn(d * a0[2], d * a0[3]);
    }
    int r1 = r0 + 1;
    if (r1 < NN) {
        float d = g_dinv[r1];
        hn1[r1 * 16 + (cg >> 1)]     = __floats2half2_rn(d * a1[0], d * a1[1]);
        hn1[r1 * 16 + (cg >> 1) + 1] = __floats2half2_rn(d * a1[2], d * a1[3]);
    }
}

// ---------------- gather core (R4 structure + int4 index loads) ----------------
// Warp per node. lane = (side<<4) | pair: pair = channel pair (2p,2p+1) as
// __half2; 16 lanes cover a 64B feature row; side ∈ {0,1} so each feature
// warp-LDG fetches 2 rows (2 edges). Per 8-edge iteration: ONE aligned int4
// index LDG (side s covers contiguous edges [e+4s, e+4s+4)) + 4 feature LDGs
// batched -> 4x128B outstanding. shfl_xor(16) merges the side accumulators.
__device__ __forceinline__ float2 gather_sum(const __half2* __restrict__ H,
                                             int node, int pair, int side) {
    float2 acc = make_float2(0.f, 0.f);
    if (side == 0) {   // self loop
        acc = __half22float2(H[node * 16 + pair]);
    }
    int e = g_off[node], end = g_cur[node];
    // prologue: align e to 4 for int4 loads (parity-split across sides)
    int r0 = (4 - (e & 3)) & 3;
    if (r0 > end - e) r0 = end - e;
    for (int j = side; j < r0; j += 2) {
        float2 f = __half22float2(H[g_csr[e + j] * 16 + pair]);
        acc.x += f.x; acc.y += f.y;
    }
    e += r0;
    // main: 8 edges per iteration
    for (; e + 8 <= end; e += 8) {
        int4 I = *(const int4*)(g_csr + e + 4 * side);   // 16B-aligned (e%4==0)
        float2 f0 = __half22float2(H[I.x * 16 + pair]);
        float2 f1 = __half22float2(H[I.y * 16 + pair]);
        float2 f2 = __half22float2(H[I.z * 16 + pair]);
        float2 f3 = __half22float2(H[I.w * 16 + pair]);
        acc.x += (f0.x + f1.x) + (f2.x + f3.x);
        acc.y += (f0.y + f1.y) + (f2.y + f3.y);
    }
    // tail: r in [0,8): side 0 -> [e, min(end,e+4)), side 1 -> [e+4, end)
    int tb = e + 4 * side;
    int te = side ? end : ((end < e + 4) ? end : e + 4);
    for (int j = tb; j < te; j++) {
        float2 f = __half22float2(H[g_csr[j] * 16 + pair]);
        acc.x += f.x; acc.y += f.y;
    }
    acc.x += __shfl_xor_sync(0xffffffffu, acc.x, 16);
    acc.y += __shfl_xor_sync(0xffffffffu, acc.y, 16);
    return acc;
}

// ---------------- agg1: p = fp16( dinv * leaky(dinv*sum + b1) ) ----------------
__global__ __launch_bounds__(256) void k_agg1(const float* __restrict__ b1) {
    int warp = (blockIdx.x * 256 + threadIdx.x) >> 5;
    int lane = threadIdx.x & 31;
    if (warp >= NN) return;
    int pair = lane & 15, side = lane >> 4;
    float2 acc = gather_sum((const __half2*)g_hn1, warp, pair, side);
    float d = g_dinv[warp];
    float2 bb = ((const float2*)b1)[pair];
    float rx = d * acc.x + bb.x;
    float ry = d * acc.y + bb.y;
    rx = (rx > 0.f) ? rx : 0.1f * rx;
    ry = (ry > 0.f) ? ry : 0.1f * ry;
    if (side == 0)
        ((__half2*)g_p)[warp * 16 + pair] = __floats2half2_rn(d * rx, d * ry);
}

// ---------------- sign-split float atomic max (no-return -> RED) ----------------
__device__ __forceinline__ void atomicMaxFloat(float* addr, float val) {
    if (val >= 0.f)
        atomicMax((int*)addr, __float_as_int(val));
    else
        atomicMin((unsigned int*)addr, __float_as_uint(val));
}

// ---------------- agg2: h2 = dinv*(q@W2) + b2 ; fused max pool ----------------
__global__ __launch_bounds__(256) void k_agg2(const float* __restrict__ W2,
                                              const float* __restrict__ b2,
                                              const int* __restrict__ batch) {
    __shared__ float2 W2s[H1 * 32];  // W2 [32][64] row-major == [32][32] float2
    for (int i = threadIdx.x; i < H1 * 32; i += 256)
        W2s[i] = ((const float2*)W2)[i];
    __syncthreads();
    int warp = (blockIdx.x * 256 + threadIdx.x) >> 5;
    int lane = threadIdx.x & 31;
    if (warp >= NN) return;
    int pair = lane & 15, side = lane >> 4;
    float2 acc = gather_sum((const __half2*)g_p, warp, pair, side);
    // q[2j] = acc.x at lane j (mod 16); q[2j+1] = acc.y; lane owns out ch 2*lane, 2*lane+1
    float z0 = 0.f, z1 = 0.f;
#pragma unroll
    for (int k = 0; k < H1; k++) {
        float qk = __shfl_sync(0xffffffffu, (k & 1) ? acc.y : acc.x, (k >> 1) & 15);
        float2 w = W2s[k * 32 + lane];
        z0 = fmaf(qk, w.x, z0);
        z1 = fmaf(qk, w.y, z1);
    }
    float d = g_dinv[warp];
    float2 bb = ((const float2*)b2)[lane];
    float ox = d * z0 + bb.x;
    float oy = d * z1 + bb.y;
    int gidx = batch[warp];
    atomicMaxFloat(&g_pool[gidx * H2 + 2 * lane], ox);
    atomicMaxFloat(&g_pool[gidx * H2 + 2 * lane + 1], oy);
}

// ---------------- MLP head: one block per graph ----------------
__global__ __launch_bounds__(128) void k_mlp(const float* __restrict__ l1W, const float* __restrict__ l1b,
                                             const float* __restrict__ l2W, const float* __restrict__ l2b,
                                             const float* __restrict__ l3W, const float* __restrict__ l3b,
                                             float* __restrict__ out) {
    __shared__ float gv[H2];
    __shared__ float z1[128];
    __shared__ float z2[64];
    int g = blockIdx.x, t = threadIdx.x;
    if (t < H2) gv[t] = g_pool[g * H2 + t];
    __syncthreads();
    {
        float s = 0.f;
#pragma unroll
        for (int k = 0; k < H2; k++) s = fmaf(gv[k], l1W[k * 128 + t], s);
        s += l1b[t];
        z1[t] = (s > 0.f) ? s : 0.1f * s;
    }
    __syncthreads();
    if (t < 64) {
        float s = 0.f;
#pragma unroll
        for (int k = 0; k < 128; k++) s = fmaf(z1[k], l2W[k * 64 + t], s);
        s += l2b[t];
        z2[t] = (s > 0.f) ? s : 0.1f * s;
    }
    __syncthreads();
    if (t < ACT) {
        float s = 0.f;
#pragma unroll
        for (int k = 0; k < 64; k++) s = fmaf(z2[k], l3W[k * ACT + t], s);
        out[g * ACT + t] = s + l3b[t];
    }
}

// ---------------- launch ----------------
extern "C" void kernel_launch(void* const* d_in, const int* in_sizes, int n_in,
                              void* d_out, int out_size) {
    const float* x    = (const float*)d_in[0];
    const int*   ei   = (const int*)d_in[1];   // [2,E]
    const int*   bat  = (const int*)d_in[2];
    const float* W1   = (const float*)d_in[3];
    const float* b1   = (const float*)d_in[4];
    const float* W2   = (const float*)d_in[5];
    const float* b2   = (const float*)d_in[6];
    const float* l1W  = (const float*)d_in[7];
    const float* l1b  = (const float*)d_in[8];
    const float* l2W  = (const float*)d_in[9];
    const float* l2b  = (const float*)d_in[10];
    const float* l3W  = (const float*)d_in[11];
    const float* l3b  = (const float*)d_in[12];
    float* out = (float*)d_out;
    const int* src = ei;
    const int* dst = ei + EE;

    void *p_deg = nullptr, *p_cnt = nullptr, *p_pool = nullptr;
    cudaGetSymbolAddress(&p_deg, g_deg);
    cudaGetSymbolAddress(&p_cnt, g_counter);
    cudaGetSymbolAddress(&p_pool, g_pool);
    cudaMemsetAsync(p_deg, 0, NN * sizeof(int));
    cudaMemsetAsync(p_cnt, 0, sizeof(int));
    cudaMemsetAsync(p_pool, 0xFF, GG * H2 * sizeof(float));  // NaN-bits: valid init for sign-split max

    const int NB_E4 = (EE / 4 + 255) / 256;       // 3125
    const int NB_N  = (NN + 255) / 256;           // 391
    const int NB_W  = (NN + 7) / 8;               // 12500 (warp per node)
    const int NB_G1 = (NN + TILE_N - 1) / TILE_N; // 1563

    k_deg<<<NB_E4, 256>>>(dst);
    k_offsets<<<NB_N, 256>>>();
    k_scatter<<<NB_E4, 256>>>(src, dst);

    k_gemm1<<<NB_G1, 256>>>(x, W1);
    k_agg1<<<NB_W, 256>>>(b1);
    k_agg2<<<NB_W, 256>>>(W2, b2, bat);

    k_mlp<<<GG, 128>>>(l1W, l1b, l2W, l2b, l3W, l3b, out);
}